// round 6
// baseline (speedup 1.0000x reference)
#include <cuda_runtime.h>

#define B_DIM 8
#define T_DIM 4000
#define D_DIM 1024
#define G_DIM 5
#define L_DIM (T_DIM / G_DIM)      // 800 tokens per slab
#define NTOK (B_DIM * T_DIM)       // 32000
#define NSLAB (B_DIM * G_DIM)      // 40
#define EPS 1e-5f
#define NV4 (D_DIM / 4)            // 256 float4 per token

#define SPC 8                      // slabs per chunk
#define NCHUNK (NSLAB / SPC)       // 5
#define TPC (SPC * L_DIM)          // 6400 tokens per chunk
#define WPB 8                      // warps (tokens) per block
#define APB (TPC / WPB)            // 800 blocks per chunk per role

// Scratch (no allocations allowed)
__device__ float g_tok_sum[NTOK];
__device__ float g_tok_sumsq[NTOK];
__device__ float g_slab_mean[NSLAB];
__device__ float g_slab_rstd[NSLAB];

// ---------------------------------------------------------------------------
// Stats role: one WARP per token, 2 batches of 4 float4 (default caching so
// the chunk survives in L2 until apply 2 launches later), shuffle reduce.
// ---------------------------------------------------------------------------
__device__ __forceinline__ void stats_role(const float4* __restrict__ x,
                                           int tok) {
    const int lane = threadIdx.x & 31;
    const size_t base = (size_t)tok * NV4 + lane;

    float s = 0.0f, ss = 0.0f;
    #pragma unroll
    for (int h = 0; h < 2; ++h) {
        float4 v0 = x[base + 128 * h];
        float4 v1 = x[base + 128 * h + 32];
        float4 v2 = x[base + 128 * h + 64];
        float4 v3 = x[base + 128 * h + 96];
        s  += (v0.x + v0.y) + (v0.z + v0.w) + (v1.x + v1.y) + (v1.z + v1.w)
            + (v2.x + v2.y) + (v2.z + v2.w) + (v3.x + v3.y) + (v3.z + v3.w);
        ss += v0.x*v0.x + v0.y*v0.y + v0.z*v0.z + v0.w*v0.w
            + v1.x*v1.x + v1.y*v1.y + v1.z*v1.z + v1.w*v1.w
            + v2.x*v2.x + v2.y*v2.y + v2.z*v2.z + v2.w*v2.w
            + v3.x*v3.x + v3.y*v3.y + v3.z*v3.z + v3.w*v3.w;
    }

    #pragma unroll
    for (int o = 16; o > 0; o >>= 1) {
        s  += __shfl_down_sync(0xffffffffu, s,  o);
        ss += __shfl_down_sync(0xffffffffu, ss, o);
    }
    if (lane == 0) {
        g_tok_sum[tok]   = s;
        g_tok_sumsq[tok] = ss;
    }
}

// ---------------------------------------------------------------------------
// Slabstats role: one block per slab, reduce 800 token partials (tiny, L2).
// ---------------------------------------------------------------------------
__device__ __forceinline__ void ss_role(int slab) {
    const int tid  = threadIdx.x;
    const int warp = tid >> 5, lane = tid & 31;
    const int sbase = slab * L_DIM;

    float s1 = g_tok_sum[sbase + tid] + g_tok_sum[sbase + tid + 256]
             + g_tok_sum[sbase + tid + 512];
    float s2 = g_tok_sumsq[sbase + tid] + g_tok_sumsq[sbase + tid + 256]
             + g_tok_sumsq[sbase + tid + 512];
    if (tid < 32) {
        s1 += g_tok_sum[sbase + 768 + tid];
        s2 += g_tok_sumsq[sbase + 768 + tid];
    }
    #pragma unroll
    for (int o = 16; o > 0; o >>= 1) {
        s1 += __shfl_down_sync(0xffffffffu, s1, o);
        s2 += __shfl_down_sync(0xffffffffu, s2, o);
    }
    __shared__ float sh1[8], sh2[8];
    if (lane == 0) { sh1[warp] = s1; sh2[warp] = s2; }
    __syncthreads();
    if (tid == 0) {
        float t1 = 0.0f, t2 = 0.0f;
        #pragma unroll
        for (int w = 0; w < 8; ++w) { t1 += sh1[w]; t2 += sh2[w]; }
        const float inv_n = 1.0f / (float)(L_DIM * D_DIM);
        const float m = t1 * inv_n;
        g_slab_mean[slab] = m;
        g_slab_rstd[slab] = rsqrtf(t2 * inv_n - m * m + EPS);
    }
}

// ---------------------------------------------------------------------------
// Apply role: warp-per-token, NO shared memory, NO syncthreads.  Slab stats
// are precomputed; per-token affine folded to y = x*A + C then *w + b.
// x re-read via __ldcs (last use, L2-hot), out via __stcs (evict-first).
// ---------------------------------------------------------------------------
__device__ __forceinline__ void apply_role(const float4* __restrict__ x,
                                           const float4* __restrict__ weight,
                                           const float4* __restrict__ bias,
                                           float4* __restrict__ out,
                                           int chunk, int blk) {
    const int warp = threadIdx.x >> 5;
    const int lane = threadIdx.x & 31;
    const int tok  = chunk * TPC + blk * WPB + warp;
    const int slab = tok / L_DIM;

    const float inv_d = 1.0f / (float)D_DIM;
    const float tm = g_tok_sum[tok] * inv_d;
    const float tv = g_tok_sumsq[tok] * inv_d - tm * tm;
    const float tr = rsqrtf(tv + EPS);
    const float gm = g_slab_mean[slab];
    const float gr = g_slab_rstd[slab];

    const float A = 0.5f * (gr + tr);
    const float C = -0.5f * (gm * gr + tm * tr);

    const size_t base = (size_t)tok * NV4 + lane;

    #pragma unroll
    for (int h = 0; h < 2; ++h) {
        float4 xs[4];
        #pragma unroll
        for (int k = 0; k < 4; ++k)
            xs[k] = __ldcs(&x[base + 128 * h + 32 * k]);
        #pragma unroll
        for (int k = 0; k < 4; ++k) {
            const float4 w  = weight[lane + 128 * h + 32 * k];
            const float4 bb = bias[lane + 128 * h + 32 * k];
            float4 o;
            o.x = fmaf(fmaf(xs[k].x, A, C), w.x, bb.x);
            o.y = fmaf(fmaf(xs[k].y, A, C), w.y, bb.y);
            o.z = fmaf(fmaf(xs[k].z, A, C), w.z, bb.z);
            o.w = fmaf(fmaf(xs[k].w, A, C), w.w, bb.w);
            __stcs(&out[base + 128 * h + 32 * k], o);
        }
    }
}

// ---------------------------------------------------------------------------
// Combined kernel.  Block ranges: [0,nA) apply(apply_c); [nA,nA+nS) ss(ss_c);
// rest stats(stats_c).  Apply first (heaviest), ss last (tiny).
// ---------------------------------------------------------------------------
__global__ void __launch_bounds__(256, 6)
fused_kernel(const float4* __restrict__ x,
             const float4* __restrict__ weight,
             const float4* __restrict__ bias,
             float4* __restrict__ out,
             int apply_c, int ss_c, int stats_c, int nA, int nS) {
    const int bid = blockIdx.x;
    if (bid < nA) {
        apply_role(x, weight, bias, out, apply_c, bid);
    } else if (bid < nA + nS) {
        ss_role(ss_c * SPC + (bid - nA));
    } else {
        const int j = bid - nA - nS;
        stats_role(x, stats_c * TPC + j * WPB + (threadIdx.x >> 5));
    }
}

// ---------------------------------------------------------------------------
extern "C" void kernel_launch(void* const* d_in, const int* in_sizes, int n_in,
                              void* d_out, int out_size) {
    const float4* x      = (const float4*)d_in[0];
    // d_in[1] = mask (dense ones; only G matters and it is fixed at 5)
    const float4* weight = (const float4*)d_in[2];
    const float4* bias   = (const float4*)d_in[3];
    float4* out          = (float4*)d_out;

    // 3-stage software pipeline over 5 chunks of 8 slabs (26.2 MB each).
    // Launch i: apply(i-2) + slabstats(i-1) + stats(i).  Kernel boundaries
    // are the producer->consumer barriers; chunks stay hot in L2 for the
    // 2 launches between stats and apply.
    fused_kernel<<<APB, 256>>>(x, weight, bias, out, -1, -1, 0, 0, 0);
    fused_kernel<<<APB + SPC, 256>>>(x, weight, bias, out, -1, 0, 1, 0, SPC);
    for (int c = 0; c <= 2; ++c) {
        fused_kernel<<<2 * APB + SPC, 256>>>(x, weight, bias, out,
                                             c, c + 1, c + 2, APB, SPC);
    }
    fused_kernel<<<APB + SPC, 256>>>(x, weight, bias, out, 3, 4, -1, APB, SPC);
    fused_kernel<<<APB, 256>>>(x, weight, bias, out, 4, -1, -1, APB, 0);
}

// round 7
// speedup vs baseline: 1.0868x; 1.0868x over previous
#include <cuda_runtime.h>

#define B_DIM 8
#define T_DIM 4000
#define D_DIM 1024
#define G_DIM 5
#define L_DIM (T_DIM / G_DIM)      // 800
#define NTOK (B_DIM * T_DIM)       // 32000
#define NGRP (B_DIM * G_DIM)       // 40
#define EPS 1e-5f
#define NV4 (D_DIM / 4)            // 256 float4 per token
#define WPB 8                      // warps (= tokens) per block

// Scratch (no allocations allowed)
__device__ float g_tok_sum[NTOK];
__device__ float g_tok_sumsq[NTOK];
__device__ float g_grp_mean[NGRP];
__device__ float g_grp_rstd[NGRP];

// ---------------------------------------------------------------------------
// Kernel 1: per-token sum / sumsq.  One WARP per token: 32 lanes x 8 float4
// (MLP=8).  Warp-shuffle reduce only — no smem, no syncthreads.
// ---------------------------------------------------------------------------
__global__ void __launch_bounds__(256, 6)
tok_stats_kernel(const float4* __restrict__ x) {
    const int tid  = threadIdx.x;
    const int warp = tid >> 5;
    const int lane = tid & 31;
    const int tok  = blockIdx.x * WPB + warp;
    const size_t base = (size_t)tok * NV4 + lane;

    float4 v0 = x[base];
    float4 v1 = x[base + 32];
    float4 v2 = x[base + 64];
    float4 v3 = x[base + 96];
    float4 v4 = x[base + 128];
    float4 v5 = x[base + 160];
    float4 v6 = x[base + 192];
    float4 v7 = x[base + 224];

    float s  = (v0.x + v0.y) + (v0.z + v0.w) + (v1.x + v1.y) + (v1.z + v1.w)
             + (v2.x + v2.y) + (v2.z + v2.w) + (v3.x + v3.y) + (v3.z + v3.w)
             + (v4.x + v4.y) + (v4.z + v4.w) + (v5.x + v5.y) + (v5.z + v5.w)
             + (v6.x + v6.y) + (v6.z + v6.w) + (v7.x + v7.y) + (v7.z + v7.w);
    float ss = v0.x*v0.x + v0.y*v0.y + v0.z*v0.z + v0.w*v0.w
             + v1.x*v1.x + v1.y*v1.y + v1.z*v1.z + v1.w*v1.w
             + v2.x*v2.x + v2.y*v2.y + v2.z*v2.z + v2.w*v2.w
             + v3.x*v3.x + v3.y*v3.y + v3.z*v3.z + v3.w*v3.w
             + v4.x*v4.x + v4.y*v4.y + v4.z*v4.z + v4.w*v4.w
             + v5.x*v5.x + v5.y*v5.y + v5.z*v5.z + v5.w*v5.w
             + v6.x*v6.x + v6.y*v6.y + v6.z*v6.z + v6.w*v6.w
             + v7.x*v7.x + v7.y*v7.y + v7.z*v7.z + v7.w*v7.w;

    #pragma unroll
    for (int o = 16; o > 0; o >>= 1) {
        s  += __shfl_down_sync(0xffffffffu, s,  o);
        ss += __shfl_down_sync(0xffffffffu, ss, o);
    }

    if (lane == 0) {
        g_tok_sum[tok]   = s;
        g_tok_sumsq[tok] = ss;
    }
}

// ---------------------------------------------------------------------------
// Kernel 2: group stats.  One block per (b, g), reduce L=800 token partials.
// ---------------------------------------------------------------------------
__global__ void grp_stats_kernel() {
    const int bg = blockIdx.x;              // 0..39
    const int tok0 = bg * L_DIM;            // slabs are contiguous
    const int tid = threadIdx.x;

    float s = 0.0f, ss = 0.0f;
    for (int i = tid; i < L_DIM; i += 256) {
        s  += g_tok_sum[tok0 + i];
        ss += g_tok_sumsq[tok0 + i];
    }

    #pragma unroll
    for (int o = 16; o > 0; o >>= 1) {
        s  += __shfl_down_sync(0xffffffffu, s,  o);
        ss += __shfl_down_sync(0xffffffffu, ss, o);
    }

    __shared__ float sh_s[8];
    __shared__ float sh_ss[8];
    const int warp = tid >> 5, lane = tid & 31;
    if (lane == 0) { sh_s[warp] = s; sh_ss[warp] = ss; }
    __syncthreads();

    if (tid == 0) {
        float ts = 0.0f, tss = 0.0f;
        #pragma unroll
        for (int w = 0; w < 8; ++w) { ts += sh_s[w]; tss += sh_ss[w]; }
        const float inv_n = 1.0f / (float)(L_DIM * D_DIM);
        const float m = ts * inv_n;
        const float v = tss * inv_n - m * m;
        g_grp_mean[bg] = m;
        g_grp_rstd[bg] = rsqrtf(v + EPS);
    }
}

// ---------------------------------------------------------------------------
// Kernel 3: apply.  One WARP per token, token order REVERSED vs tok_stats so
// early waves hit the L2-resident tail of x.  2 batches of 4 float4 keep the
// live register set small (occ 6 blocks/SM).  __ldcs re-reads (last use),
// __stcs writes (evict-first: out must not evict x from L2).
// ---------------------------------------------------------------------------
__global__ void __launch_bounds__(256, 6)
apply_kernel(const float4* __restrict__ x,
             const float4* __restrict__ weight,
             const float4* __restrict__ bias,
             float4* __restrict__ out) {
    const int tid  = threadIdx.x;
    const int warp = tid >> 5;
    const int lane = tid & 31;
    const int tok  = NTOK - 1 - (blockIdx.x * WPB + warp);   // descending

    const int bg = tok / L_DIM;            // slab index (contiguous groups)

    const float inv_d = 1.0f / (float)D_DIM;
    const float tm = g_tok_sum[tok] * inv_d;
    const float tv = g_tok_sumsq[tok] * inv_d - tm * tm;
    const float tr = rsqrtf(tv + EPS);
    const float gm = g_grp_mean[bg];
    const float gr = g_grp_rstd[bg];

    const float A = 0.5f * (gr + tr);
    const float C = -0.5f * (gm * gr + tm * tr);

    const size_t base = (size_t)tok * NV4 + lane;

    #pragma unroll
    for (int h = 0; h < 2; ++h) {
        const size_t b0 = base + 128 * h;
        // 4 x-loads issued back-to-back (MLP=4), then consume
        float4 x0 = __ldcs(&x[b0]);
        float4 x1 = __ldcs(&x[b0 + 32]);
        float4 x2 = __ldcs(&x[b0 + 64]);
        float4 x3 = __ldcs(&x[b0 + 96]);

        const int wi = lane + 128 * h;
        float4 w, bb, o;

        w = weight[wi];        bb = bias[wi];
        o.x = fmaf(fmaf(x0.x, A, C), w.x, bb.x);
        o.y = fmaf(fmaf(x0.y, A, C), w.y, bb.y);
        o.z = fmaf(fmaf(x0.z, A, C), w.z, bb.z);
        o.w = fmaf(fmaf(x0.w, A, C), w.w, bb.w);
        __stcs(&out[b0], o);

        w = weight[wi + 32];   bb = bias[wi + 32];
        o.x = fmaf(fmaf(x1.x, A, C), w.x, bb.x);
        o.y = fmaf(fmaf(x1.y, A, C), w.y, bb.y);
        o.z = fmaf(fmaf(x1.z, A, C), w.z, bb.z);
        o.w = fmaf(fmaf(x1.w, A, C), w.w, bb.w);
        __stcs(&out[b0 + 32], o);

        w = weight[wi + 64];   bb = bias[wi + 64];
        o.x = fmaf(fmaf(x2.x, A, C), w.x, bb.x);
        o.y = fmaf(fmaf(x2.y, A, C), w.y, bb.y);
        o.z = fmaf(fmaf(x2.z, A, C), w.z, bb.z);
        o.w = fmaf(fmaf(x2.w, A, C), w.w, bb.w);
        __stcs(&out[b0 + 64], o);

        w = weight[wi + 96];   bb = bias[wi + 96];
        o.x = fmaf(fmaf(x3.x, A, C), w.x, bb.x);
        o.y = fmaf(fmaf(x3.y, A, C), w.y, bb.y);
        o.z = fmaf(fmaf(x3.z, A, C), w.z, bb.z);
        o.w = fmaf(fmaf(x3.w, A, C), w.w, bb.w);
        __stcs(&out[b0 + 96], o);
    }
}

// ---------------------------------------------------------------------------
extern "C" void kernel_launch(void* const* d_in, const int* in_sizes, int n_in,
                              void* d_out, int out_size) {
    const float4* x      = (const float4*)d_in[0];
    // d_in[1] = mask (dense ones; only G matters and it is fixed at 5)
    const float4* weight = (const float4*)d_in[2];
    const float4* bias   = (const float4*)d_in[3];
    float4* out          = (float4*)d_out;

    tok_stats_kernel<<<NTOK / WPB, 32 * WPB>>>(x);
    grp_stats_kernel<<<NGRP, 256>>>();
    apply_kernel<<<NTOK / WPB, 32 * WPB>>>(x, weight, bias, out);
}

// round 8
// speedup vs baseline: 1.1210x; 1.0315x over previous
#include <cuda_runtime.h>

#define B_DIM 8
#define T_DIM 4000
#define D_DIM 1024
#define G_DIM 5
#define L_DIM (T_DIM / G_DIM)      // 800
#define NTOK (B_DIM * T_DIM)       // 32000
#define NGRP (B_DIM * G_DIM)       // 40
#define EPS 1e-5f
#define NV4 (D_DIM / 4)            // 256 float4 per token
#define WPB 8                      // warps per block (kernel 1)
#define TPB_A 32                   // tokens per block (kernel 3)

// Scratch (no allocations allowed)
__device__ float g_tok_sum[NTOK];
__device__ float g_tok_sumsq[NTOK];
__device__ float2 g_AC[NTOK];      // per-token affine: y = x*A + C

// ---------------------------------------------------------------------------
// Kernel 1: per-token sum / sumsq.  One WARP per token: 32 lanes x 8 float4
// (MLP=8).  Warp-shuffle reduce only.
// ---------------------------------------------------------------------------
__global__ void __launch_bounds__(256, 6)
tok_stats_kernel(const float4* __restrict__ x) {
    const int tid  = threadIdx.x;
    const int warp = tid >> 5;
    const int lane = tid & 31;
    const int tok  = blockIdx.x * WPB + warp;
    const size_t base = (size_t)tok * NV4 + lane;

    float4 v0 = x[base];
    float4 v1 = x[base + 32];
    float4 v2 = x[base + 64];
    float4 v3 = x[base + 96];
    float4 v4 = x[base + 128];
    float4 v5 = x[base + 160];
    float4 v6 = x[base + 192];
    float4 v7 = x[base + 224];

    float s  = (v0.x + v0.y) + (v0.z + v0.w) + (v1.x + v1.y) + (v1.z + v1.w)
             + (v2.x + v2.y) + (v2.z + v2.w) + (v3.x + v3.y) + (v3.z + v3.w)
             + (v4.x + v4.y) + (v4.z + v4.w) + (v5.x + v5.y) + (v5.z + v5.w)
             + (v6.x + v6.y) + (v6.z + v6.w) + (v7.x + v7.y) + (v7.z + v7.w);
    float ss = v0.x*v0.x + v0.y*v0.y + v0.z*v0.z + v0.w*v0.w
             + v1.x*v1.x + v1.y*v1.y + v1.z*v1.z + v1.w*v1.w
             + v2.x*v2.x + v2.y*v2.y + v2.z*v2.z + v2.w*v2.w
             + v3.x*v3.x + v3.y*v3.y + v3.z*v3.z + v3.w*v3.w
             + v4.x*v4.x + v4.y*v4.y + v4.z*v4.z + v4.w*v4.w
             + v5.x*v5.x + v5.y*v5.y + v5.z*v5.z + v5.w*v5.w
             + v6.x*v6.x + v6.y*v6.y + v6.z*v6.z + v6.w*v6.w
             + v7.x*v7.x + v7.y*v7.y + v7.z*v7.z + v7.w*v7.w;

    #pragma unroll
    for (int o = 16; o > 0; o >>= 1) {
        s  += __shfl_down_sync(0xffffffffu, s,  o);
        ss += __shfl_down_sync(0xffffffffu, ss, o);
    }

    if (lane == 0) {
        g_tok_sum[tok]   = s;
        g_tok_sumsq[tok] = ss;
    }
}

// ---------------------------------------------------------------------------
// Kernel 2: one block per slab: reduce 800 token partials -> slab mean/rstd,
// then precompute the per-token affine (A, C) for all 800 tokens:
//   0.5*gr*(x-gm) + 0.5*tr*(x-tm) = x*A + C
// All traffic is L2-resident partials (~256KB) + 256KB AC writes.
// ---------------------------------------------------------------------------
__global__ void __launch_bounds__(256)
grp_ac_kernel() {
    const int bg = blockIdx.x;              // 0..39 (slabs contiguous)
    const int tok0 = bg * L_DIM;
    const int tid = threadIdx.x;
    const int warp = tid >> 5, lane = tid & 31;

    float s = 0.0f, ss = 0.0f;
    #pragma unroll
    for (int i = 0; i < 3; ++i) {
        s  += g_tok_sum[tok0 + tid + 256 * i];
        ss += g_tok_sumsq[tok0 + tid + 256 * i];
    }
    if (tid < 32) {
        s  += g_tok_sum[tok0 + 768 + tid];
        ss += g_tok_sumsq[tok0 + 768 + tid];
    }

    #pragma unroll
    for (int o = 16; o > 0; o >>= 1) {
        s  += __shfl_down_sync(0xffffffffu, s,  o);
        ss += __shfl_down_sync(0xffffffffu, ss, o);
    }

    __shared__ float sh_s[8], sh_ss[8];
    __shared__ float sh_gm, sh_gr;
    if (lane == 0) { sh_s[warp] = s; sh_ss[warp] = ss; }
    __syncthreads();
    if (tid == 0) {
        float ts = 0.0f, tss = 0.0f;
        #pragma unroll
        for (int w = 0; w < 8; ++w) { ts += sh_s[w]; tss += sh_ss[w]; }
        const float inv_n = 1.0f / (float)(L_DIM * D_DIM);
        const float m = ts * inv_n;
        sh_gm = m;
        sh_gr = rsqrtf(tss * inv_n - m * m + EPS);
    }
    __syncthreads();
    const float gm = sh_gm;
    const float gr = sh_gr;

    const float inv_d = 1.0f / (float)D_DIM;
    #pragma unroll
    for (int i = 0; i < 4; ++i) {
        const int j = tid + 256 * i;
        if (j < L_DIM) {
            const int tok = tok0 + j;
            const float tm = g_tok_sum[tok] * inv_d;
            const float tv = g_tok_sumsq[tok] * inv_d - tm * tm;
            const float tr = rsqrtf(tv + EPS);
            float2 ac;
            ac.x = 0.5f * (gr + tr);
            ac.y = -0.5f * (gm * gr + tm * tr);
            g_AC[tok] = ac;
        }
    }
}

// ---------------------------------------------------------------------------
// Kernel 3: apply, thread-per-feature.  Thread tid owns float4 feature slot
// tid; weight/bias live in registers for the whole block (loaded ONCE).
// Block processes 32 tokens; inner loop: 1 broadcast LDG.64 (A,C) +
// 1 LDG.128 (__ldcs x) + 1 STG.128 (__stcs out) per token.  Token order is
// descending so early blocks hit the L2-resident tail of x from kernel 1.
// ---------------------------------------------------------------------------
__global__ void __launch_bounds__(256)
apply_kernel(const float4* __restrict__ x,
             const float4* __restrict__ weight,
             const float4* __restrict__ bias,
             float4* __restrict__ out) {
    const int tid = threadIdx.x;

    const float4 w  = weight[tid];   // loaded once, live in regs
    const float4 bb = bias[tid];

    const int tok_hi = NTOK - blockIdx.x * TPB_A;   // exclusive upper bound

    #pragma unroll 4
    for (int i = 0; i < TPB_A; ++i) {
        const int tok = tok_hi - 1 - i;             // descending
        const float2 ac = g_AC[tok];                // broadcast across block
        const size_t idx = (size_t)tok * NV4 + tid;
        const float4 xv = __ldcs(&x[idx]);          // last use: evict-first
        float4 o;
        o.x = fmaf(fmaf(xv.x, ac.x, ac.y), w.x, bb.x);
        o.y = fmaf(fmaf(xv.y, ac.x, ac.y), w.y, bb.y);
        o.z = fmaf(fmaf(xv.z, ac.x, ac.y), w.z, bb.z);
        o.w = fmaf(fmaf(xv.w, ac.x, ac.y), w.w, bb.w);
        __stcs(&out[idx], o);                       // streaming store
    }
}

// ---------------------------------------------------------------------------
extern "C" void kernel_launch(void* const* d_in, const int* in_sizes, int n_in,
                              void* d_out, int out_size) {
    const float4* x      = (const float4*)d_in[0];
    // d_in[1] = mask (dense ones; only G matters and it is fixed at 5)
    const float4* weight = (const float4*)d_in[2];
    const float4* bias   = (const float4*)d_in[3];
    float4* out          = (float4*)d_out;

    tok_stats_kernel<<<NTOK / WPB, 32 * WPB>>>(x);
    grp_ac_kernel<<<NGRP, 256>>>();
    apply_kernel<<<NTOK / TPB_A, 256>>>(x, weight, bias, out);
}